// round 1
// baseline (speedup 1.0000x reference)
#include <cuda_runtime.h>
#include <math.h>

#define BATCH   8
#define SEQ     2048
#define DIM     512
#define HEADS   8
#define DH      64
#define HID     512
#define TOK     (BATCH*SEQ)      /* 16384 */
#define QKVN    (3*HID)          /* 1536 */
#define SPAD    68

// Scratch (static device arrays — allocation inside kernel_launch is forbidden)
__device__ __align__(256) float g_xn[(size_t)TOK*DIM];
__device__ __align__(256) float g_q[(size_t)TOK*HID];   // [b][h][n][d]
__device__ __align__(256) float g_k[(size_t)TOK*HID];
__device__ __align__(256) float g_v[(size_t)TOK*HID];
__device__ __align__(256) float g_o[(size_t)TOK*HID];   // [token][h*64+d]

// ---------------------------------------------------------------------------
// 1) RMSNorm: xn = x / max(||x||,eps) * g * sqrt(512)
// ---------------------------------------------------------------------------
__global__ void rmsnorm_kernel(const float* __restrict__ x,
                               const float* __restrict__ g) {
    int row = blockIdx.x;
    const float4* xr = (const float4*)(x + (size_t)row * DIM);
    float4* outr = (float4*)(g_xn + (size_t)row * DIM);
    int tid = threadIdx.x;            // 128 threads, 4 floats each
    float4 xv = xr[tid];
    float ss = xv.x*xv.x + xv.y*xv.y + xv.z*xv.z + xv.w*xv.w;
    #pragma unroll
    for (int m = 16; m; m >>= 1) ss += __shfl_xor_sync(0xffffffffu, ss, m);
    __shared__ float sred[4];
    int warp = tid >> 5, lane = tid & 31;
    if (lane == 0) sred[warp] = ss;
    __syncthreads();
    ss = sred[0] + sred[1] + sred[2] + sred[3];
    float inv = 22.627416997969522f / fmaxf(sqrtf(ss), 1e-12f); // sqrt(512)/norm
    float4 gv = ((const float4*)g)[tid];
    float4 o;
    o.x = xv.x * inv * gv.x;
    o.y = xv.y * inv * gv.y;
    o.z = xv.z * inv * gv.z;
    o.w = xv.w * inv * gv.w;
    outr[tid] = o;
}

// ---------------------------------------------------------------------------
// 2) SGEMM 128x128x16 tiles, 256 threads, 8x8 per thread
//    MODE 0: C[row*N+col] plain store
//    MODE 1: scatter to g_q / g_k / g_v in [b][h][n][d] layout
// ---------------------------------------------------------------------------
template <int MODE>
__device__ __forceinline__ void sgemm_body(const float* __restrict__ A,
                                           const float* __restrict__ Bm,
                                           float* __restrict__ C,
                                           int N, int K) {
    __shared__ float As[16][132];
    __shared__ float Bs[16][128];
    int tid = threadIdx.x;
    int rm = (tid >> 4) << 3;      // 0..120
    int rn = (tid & 15) << 3;      // 0..120
    int arow = tid >> 2, acol = (tid & 3) << 2;
    int brow = tid >> 5, bcol = (tid & 31) << 2;
    const float* Aptr = A + (size_t)(blockIdx.y * 128 + arow) * K + acol;
    const float* Bptr = Bm + (size_t)brow * N + blockIdx.x * 128 + bcol;

    float acc[8][8];
    #pragma unroll
    for (int i = 0; i < 8; i++)
        #pragma unroll
        for (int j = 0; j < 8; j++) acc[i][j] = 0.0f;

    for (int kb = 0; kb < K; kb += 16) {
        #pragma unroll
        for (int p = 0; p < 2; p++) {
            float4 av = *(const float4*)(Aptr + (size_t)p * 64 * K + kb);
            As[acol + 0][arow + p * 64] = av.x;
            As[acol + 1][arow + p * 64] = av.y;
            As[acol + 2][arow + p * 64] = av.z;
            As[acol + 3][arow + p * 64] = av.w;
        }
        #pragma unroll
        for (int p = 0; p < 2; p++) {
            float4 bv = *(const float4*)(Bptr + (size_t)(kb + p * 8) * N);
            *(float4*)&Bs[brow + p * 8][bcol] = bv;
        }
        __syncthreads();
        #pragma unroll
        for (int k = 0; k < 16; k++) {
            float4 a0 = *(const float4*)&As[k][rm];
            float4 a1 = *(const float4*)&As[k][rm + 4];
            float4 b0 = *(const float4*)&Bs[k][rn];
            float4 b1 = *(const float4*)&Bs[k][rn + 4];
            float a[8] = {a0.x, a0.y, a0.z, a0.w, a1.x, a1.y, a1.z, a1.w};
            float b[8] = {b0.x, b0.y, b0.z, b0.w, b1.x, b1.y, b1.z, b1.w};
            #pragma unroll
            for (int i = 0; i < 8; i++)
                #pragma unroll
                for (int j = 0; j < 8; j++) acc[i][j] += a[i] * b[j];
        }
        __syncthreads();
    }

    if (MODE == 0) {
        #pragma unroll
        for (int i = 0; i < 8; i++) {
            float* cp = C + (size_t)(blockIdx.y * 128 + rm + i) * N
                          + blockIdx.x * 128 + rn;
            *(float4*)cp = make_float4(acc[i][0], acc[i][1], acc[i][2], acc[i][3]);
            *(float4*)(cp + 4) = make_float4(acc[i][4], acc[i][5], acc[i][6], acc[i][7]);
        }
    } else {
        #pragma unroll
        for (int i = 0; i < 8; i++) {
            int row = blockIdx.y * 128 + rm + i;
            int bb = row >> 11, nn = row & 2047;
            #pragma unroll
            for (int j = 0; j < 8; j++) {
                int col = blockIdx.x * 128 + rn + j;
                int which = col >> 9;
                int hh = (col >> 6) & 7;
                int d = col & 63;
                float* dst = (which == 0) ? g_q : (which == 1) ? g_k : g_v;
                dst[(((size_t)((bb << 3) + hh) * SEQ + nn) << 6) + d] = acc[i][j];
            }
        }
    }
}

__global__ void qkv_gemm_kernel(const float* __restrict__ w) {
    sgemm_body<1>(g_xn, w, nullptr, QKVN, DIM);
}
__global__ void out_gemm_kernel(const float* __restrict__ w, float* __restrict__ out) {
    sgemm_body<0>(g_o, w, out, DIM, HID);
}

// ---------------------------------------------------------------------------
// 3) per-head L2 norm of q/k rows (64 wide), one warp per row
//    mult folds attention SCALE=8 into q
// ---------------------------------------------------------------------------
__global__ void qknorm_kernel(const float* __restrict__ scale, float mult, int which) {
    float* buf = which ? g_k : g_q;
    int gw = blockIdx.x * 8 + (threadIdx.x >> 5);  // global warp == row
    int lane = threadIdx.x & 31;
    float2* r = (float2*)(buf + (size_t)gw * DH);
    float2 v = r[lane];
    float ss = v.x * v.x + v.y * v.y;
    #pragma unroll
    for (int m = 16; m; m >>= 1) ss += __shfl_xor_sync(0xffffffffu, ss, m);
    float inv = mult / fmaxf(sqrtf(ss), 1e-12f);
    v.x *= inv * scale[lane * 2];
    v.y *= inv * scale[lane * 2 + 1];
    r[lane] = v;
}

// ---------------------------------------------------------------------------
// 4) Flash attention: 64-query tile per block, loop 64-key blocks
//    grid (SEQ/64, B*H), 256 threads, dynamic smem 4*64*68*4 = 69632 B
// ---------------------------------------------------------------------------
extern __shared__ float smem_attn[];
__global__ void attn_kernel() {
    float* Qs = smem_attn;             // [64][SPAD]
    float* Kt = Qs + 64 * SPAD;        // [d][key]
    float* Vs = Kt + 64 * SPAD;        // [key][d]
    float* Ps = Vs + 64 * SPAD;        // [row][key]

    int bh = blockIdx.y;
    int q0 = blockIdx.x << 6;
    const float* Q = g_q + ((size_t)bh * SEQ + q0) * DH;
    const float* K = g_k + (size_t)bh * SEQ * DH;
    const float* V = g_v + (size_t)bh * SEQ * DH;

    int tid = threadIdx.x;
    int ty = tid >> 4, tx = tid & 15;
    int r0 = ty << 2, c0 = tx << 2;

    // load Q tile (contiguous 4096 floats)
    #pragma unroll
    for (int p = 0; p < 4; p++) {
        int idx = tid + p * 256;
        int row = idx >> 4, col4 = idx & 15;
        float4 v = ((const float4*)Q)[idx];
        *(float4*)&Qs[row * SPAD + col4 * 4] = v;
    }

    float mval[4], lval[4], O[4][4];
    #pragma unroll
    for (int i = 0; i < 4; i++) {
        mval[i] = -INFINITY; lval[i] = 0.0f;
        #pragma unroll
        for (int j = 0; j < 4; j++) O[i][j] = 0.0f;
    }

    for (int j0 = 0; j0 < SEQ; j0 += 64) {
        __syncthreads();  // protect Kt/Vs/Ps from prior-iter readers
        #pragma unroll
        for (int p = 0; p < 4; p++) {
            int idx = tid + p * 256;
            int row = idx >> 4, c4 = (idx & 15) << 2;
            float4 kv = ((const float4*)(K + (size_t)(j0 + row) * DH))[idx & 15];
            Kt[(c4 + 0) * SPAD + row] = kv.x;
            Kt[(c4 + 1) * SPAD + row] = kv.y;
            Kt[(c4 + 2) * SPAD + row] = kv.z;
            Kt[(c4 + 3) * SPAD + row] = kv.w;
            float4 vv = ((const float4*)(V + (size_t)(j0 + row) * DH))[idx & 15];
            *(float4*)&Vs[row * SPAD + c4] = vv;
        }
        __syncthreads();

        // S = Q K^T   (Q already scaled by 8 in qknorm)
        float S[4][4];
        #pragma unroll
        for (int i = 0; i < 4; i++)
            #pragma unroll
            for (int j = 0; j < 4; j++) S[i][j] = 0.0f;

        #pragma unroll
        for (int d = 0; d < 64; d += 4) {
            float4 a[4], b[4];
            #pragma unroll
            for (int i = 0; i < 4; i++) a[i] = *(float4*)&Qs[(r0 + i) * SPAD + d];
            #pragma unroll
            for (int t = 0; t < 4; t++) b[t] = *(float4*)&Kt[(d + t) * SPAD + c0];
            #pragma unroll
            for (int i = 0; i < 4; i++) {
                S[i][0] += a[i].x*b[0].x + a[i].y*b[1].x + a[i].z*b[2].x + a[i].w*b[3].x;
                S[i][1] += a[i].x*b[0].y + a[i].y*b[1].y + a[i].z*b[2].y + a[i].w*b[3].y;
                S[i][2] += a[i].x*b[0].z + a[i].y*b[1].z + a[i].z*b[2].z + a[i].w*b[3].z;
                S[i][3] += a[i].x*b[0].w + a[i].y*b[1].w + a[i].z*b[2].w + a[i].w*b[3].w;
            }
        }

        // online softmax (row stats reduced across the 16 tx lanes)
        #pragma unroll
        for (int i = 0; i < 4; i++) {
            float rmax = fmaxf(fmaxf(S[i][0], S[i][1]), fmaxf(S[i][2], S[i][3]));
            #pragma unroll
            for (int msk = 8; msk; msk >>= 1)
                rmax = fmaxf(rmax, __shfl_xor_sync(0xffffffffu, rmax, msk));
            float mn = fmaxf(mval[i], rmax);
            float corr = __expf(mval[i] - mn);
            mval[i] = mn;
            float rsum = 0.0f;
            #pragma unroll
            for (int j = 0; j < 4; j++) {
                float p = __expf(S[i][j] - mn);
                S[i][j] = p; rsum += p;
            }
            #pragma unroll
            for (int msk = 8; msk; msk >>= 1)
                rsum += __shfl_xor_sync(0xffffffffu, rsum, msk);
            lval[i] = lval[i] * corr + rsum;
            #pragma unroll
            for (int j = 0; j < 4; j++) O[i][j] *= corr;
            *(float4*)&Ps[(r0 + i) * SPAD + c0] =
                make_float4(S[i][0], S[i][1], S[i][2], S[i][3]);
        }
        __syncthreads();

        // O += P V
        #pragma unroll 4
        for (int k = 0; k < 64; k++) {
            float4 v4 = *(float4*)&Vs[k * SPAD + c0];
            #pragma unroll
            for (int i = 0; i < 4; i++) {
                float p = Ps[(r0 + i) * SPAD + k];
                O[i][0] += p * v4.x;
                O[i][1] += p * v4.y;
                O[i][2] += p * v4.z;
                O[i][3] += p * v4.w;
            }
        }
    }

    // epilogue: O/l, write token-major [token][h*64+d]
    int b = bh >> 3, h = bh & 7;
    #pragma unroll
    for (int i = 0; i < 4; i++) {
        float invl = 1.0f / lval[i];
        int n = q0 + r0 + i;
        float* op = g_o + ((size_t)(b * SEQ + n)) * HID + h * DH + c0;
        *(float4*)op = make_float4(O[i][0]*invl, O[i][1]*invl, O[i][2]*invl, O[i][3]*invl);
    }
}

// ---------------------------------------------------------------------------
extern "C" void kernel_launch(void* const* d_in, const int* in_sizes, int n_in,
                              void* d_out, int out_size) {
    const float* x       = (const float*)d_in[0];
    const float* g       = (const float*)d_in[1];
    const float* w_qkv   = (const float*)d_in[2];
    const float* q_scale = (const float*)d_in[3];
    const float* k_scale = (const float*)d_in[4];
    const float* w_out   = (const float*)d_in[5];
    float* out = (float*)d_out;
    (void)in_sizes; (void)n_in; (void)out_size;

    const int attn_smem = 4 * 64 * SPAD * (int)sizeof(float);  // 69632
    cudaFuncSetAttribute(attn_kernel,
                         cudaFuncAttributeMaxDynamicSharedMemorySize, attn_smem);

    rmsnorm_kernel<<<TOK, 128>>>(x, g);
    qkv_gemm_kernel<<<dim3(QKVN / 128, TOK / 128), 256>>>(w_qkv);
    qknorm_kernel<<<TOK, 256>>>(q_scale, 8.0f, 0);   // Q, SCALE folded
    qknorm_kernel<<<TOK, 256>>>(k_scale, 1.0f, 1);   // K
    attn_kernel<<<dim3(SEQ / 64, BATCH * HEADS), 256, attn_smem>>>();
    out_gemm_kernel<<<dim3(DIM / 128, TOK / 128), 256>>>(w_out, out);
}

// round 4
// speedup vs baseline: 1.9610x; 1.9610x over previous
#include <cuda_runtime.h>
#include <cuda_bf16.h>
#include <cstdint>
#include <cstddef>
#include <math.h>

#define BATCH   8
#define SEQ     2048
#define DIM     512
#define HEADS   8
#define DH      64
#define HID     512
#define TOK     (BATCH*SEQ)          /* 16384 */
#define QKVN    (3*HID)              /* 1536 */
#define NROWS   (TOK*HEADS)          /* 131072 q/k rows of 64 */

// Scratch (static device arrays — allocation inside kernel_launch is forbidden)
__device__ __align__(256) float g_xn[(size_t)TOK*DIM];
__device__ __align__(256) float g_q[(size_t)TOK*HID];   // [b][h][n][d] fp32
__device__ __align__(256) float g_k[(size_t)TOK*HID];
__device__ __align__(256) float g_v[(size_t)TOK*HID];
__device__ __align__(256) float g_o[(size_t)TOK*HID];   // [token][h*64+d]
// bf16 hi/lo packed pairs (uint32 = 2 bf16)
__device__ __align__(256) uint32_t g_qh32[(size_t)NROWS*32];
__device__ __align__(256) uint32_t g_ql32[(size_t)NROWS*32];
__device__ __align__(256) uint32_t g_kh32[(size_t)NROWS*32];
__device__ __align__(256) uint32_t g_kl32[(size_t)NROWS*32];
__device__ __align__(256) uint32_t g_vth32[(size_t)BATCH*HEADS*DH*(SEQ/2)]; // [bh][d][key/2]
__device__ __align__(256) uint32_t g_vtl32[(size_t)BATCH*HEADS*DH*(SEQ/2)];

// ---------------------------------------------------------------------------
// helpers
// ---------------------------------------------------------------------------
__device__ __forceinline__ uint32_t pack_bf16(float lo, float hi) {
    uint32_t r;
    asm("cvt.rn.bf16x2.f32 %0, %1, %2;" : "=r"(r) : "f"(hi), "f"(lo));
    return r;
}
__device__ __forceinline__ uint32_t residual_pack(uint32_t h, float e0, float e1) {
    float f0 = __uint_as_float(h << 16);
    float f1 = __uint_as_float(h & 0xFFFF0000u);
    return pack_bf16(e0 - f0, e1 - f1);
}
__device__ __forceinline__ void mma16816(float* c, const uint32_t* a,
                                         uint32_t b0, uint32_t b1) {
    asm volatile("mma.sync.aligned.m16n8k16.row.col.f32.bf16.bf16.f32 "
        "{%0,%1,%2,%3}, {%4,%5,%6,%7}, {%8,%9}, {%0,%1,%2,%3};"
        : "+f"(c[0]), "+f"(c[1]), "+f"(c[2]), "+f"(c[3])
        : "r"(a[0]), "r"(a[1]), "r"(a[2]), "r"(a[3]), "r"(b0), "r"(b1));
}
__device__ __forceinline__ void ldsm4(uint32_t* r, uint32_t a) {
    asm volatile("ldmatrix.sync.aligned.m8n8.x4.shared.b16 {%0,%1,%2,%3}, [%4];"
        : "=r"(r[0]), "=r"(r[1]), "=r"(r[2]), "=r"(r[3]) : "r"(a));
}
__device__ __forceinline__ uint32_t smem_u32(const void* p) {
    uint32_t a;
    asm("{ .reg .u64 t; cvta.to.shared.u64 t, %1; cvt.u32.u64 %0, t; }"
        : "=r"(a) : "l"(p));
    return a;
}
__device__ __forceinline__ float ex2f(float x) {
    float y; asm("ex2.approx.f32 %0, %1;" : "=f"(y) : "f"(x)); return y;
}

// ---------------------------------------------------------------------------
// 1) RMSNorm
// ---------------------------------------------------------------------------
__global__ void rmsnorm_kernel(const float* __restrict__ x,
                               const float* __restrict__ g) {
    int row = blockIdx.x;
    const float4* xr = (const float4*)(x + (size_t)row * DIM);
    float4* outr = (float4*)(g_xn + (size_t)row * DIM);
    int tid = threadIdx.x;
    float4 xv = xr[tid];
    float ss = xv.x*xv.x + xv.y*xv.y + xv.z*xv.z + xv.w*xv.w;
    #pragma unroll
    for (int m = 16; m; m >>= 1) ss += __shfl_xor_sync(0xffffffffu, ss, m);
    __shared__ float sred[4];
    int warp = tid >> 5, lane = tid & 31;
    if (lane == 0) sred[warp] = ss;
    __syncthreads();
    ss = sred[0] + sred[1] + sred[2] + sred[3];
    float inv = 22.627416997969522f / fmaxf(sqrtf(ss), 1e-12f);
    float4 gv = ((const float4*)g)[tid];
    float4 o;
    o.x = xv.x * inv * gv.x;
    o.y = xv.y * inv * gv.y;
    o.z = xv.z * inv * gv.z;
    o.w = xv.w * inv * gv.w;
    outr[tid] = o;
}

// ---------------------------------------------------------------------------
// 2) SGEMM 128x128x16 tiles (fp32, unchanged)
// ---------------------------------------------------------------------------
template <int MODE>
__device__ __forceinline__ void sgemm_body(const float* __restrict__ A,
                                           const float* __restrict__ Bm,
                                           float* __restrict__ C,
                                           int N, int K) {
    __shared__ float As[16][132];
    __shared__ float Bs[16][128];
    int tid = threadIdx.x;
    int rm = (tid >> 4) << 3;
    int rn = (tid & 15) << 3;
    int arow = tid >> 2, acol = (tid & 3) << 2;
    int brow = tid >> 5, bcol = (tid & 31) << 2;
    const float* Aptr = A + (size_t)(blockIdx.y * 128 + arow) * K + acol;
    const float* Bptr = Bm + (size_t)brow * N + blockIdx.x * 128 + bcol;

    float acc[8][8];
    #pragma unroll
    for (int i = 0; i < 8; i++)
        #pragma unroll
        for (int j = 0; j < 8; j++) acc[i][j] = 0.0f;

    for (int kb = 0; kb < K; kb += 16) {
        #pragma unroll
        for (int p = 0; p < 2; p++) {
            float4 av = *(const float4*)(Aptr + (size_t)p * 64 * K + kb);
            As[acol + 0][arow + p * 64] = av.x;
            As[acol + 1][arow + p * 64] = av.y;
            As[acol + 2][arow + p * 64] = av.z;
            As[acol + 3][arow + p * 64] = av.w;
        }
        #pragma unroll
        for (int p = 0; p < 2; p++) {
            float4 bv = *(const float4*)(Bptr + (size_t)(kb + p * 8) * N);
            *(float4*)&Bs[brow + p * 8][bcol] = bv;
        }
        __syncthreads();
        #pragma unroll
        for (int k = 0; k < 16; k++) {
            float4 a0 = *(const float4*)&As[k][rm];
            float4 a1 = *(const float4*)&As[k][rm + 4];
            float4 b0 = *(const float4*)&Bs[k][rn];
            float4 b1 = *(const float4*)&Bs[k][rn + 4];
            float a[8] = {a0.x, a0.y, a0.z, a0.w, a1.x, a1.y, a1.z, a1.w};
            float b[8] = {b0.x, b0.y, b0.z, b0.w, b1.x, b1.y, b1.z, b1.w};
            #pragma unroll
            for (int i = 0; i < 8; i++)
                #pragma unroll
                for (int j = 0; j < 8; j++) acc[i][j] += a[i] * b[j];
        }
        __syncthreads();
    }

    if (MODE == 0) {
        #pragma unroll
        for (int i = 0; i < 8; i++) {
            float* cp = C + (size_t)(blockIdx.y * 128 + rm + i) * N
                          + blockIdx.x * 128 + rn;
            *(float4*)cp = make_float4(acc[i][0], acc[i][1], acc[i][2], acc[i][3]);
            *(float4*)(cp + 4) = make_float4(acc[i][4], acc[i][5], acc[i][6], acc[i][7]);
        }
    } else {
        #pragma unroll
        for (int i = 0; i < 8; i++) {
            int row = blockIdx.y * 128 + rm + i;
            int bb = row >> 11, nn = row & 2047;
            #pragma unroll
            for (int j = 0; j < 8; j++) {
                int col = blockIdx.x * 128 + rn + j;
                int which = col >> 9;
                int hh = (col >> 6) & 7;
                int d = col & 63;
                float* dst = (which == 0) ? g_q : (which == 1) ? g_k : g_v;
                dst[(((size_t)((bb << 3) + hh) * SEQ + nn) << 6) + d] = acc[i][j];
            }
        }
    }
}

__global__ void qkv_gemm_kernel(const float* __restrict__ w) {
    sgemm_body<1>(g_xn, w, nullptr, QKVN, DIM);
}
__global__ void out_gemm_kernel(const float* __restrict__ w, float* __restrict__ out) {
    sgemm_body<0>(g_o, w, out, DIM, HID);
}

// ---------------------------------------------------------------------------
// 3) q/k prep: L2-norm row (SCALE folded into q), emit bf16 hi/lo pairs
//    one warp per 64-wide row
// ---------------------------------------------------------------------------
__global__ void qk_prep_kernel(const float* __restrict__ scale, float mult, int which) {
    const float* src = which ? g_k : g_q;
    uint32_t* dh = which ? g_kh32 : g_qh32;
    uint32_t* dl = which ? g_kl32 : g_ql32;
    int gw = blockIdx.x * 8 + (threadIdx.x >> 5);
    int lane = threadIdx.x & 31;
    float2 v = ((const float2*)(src + (size_t)gw * DH))[lane];
    float ss = v.x * v.x + v.y * v.y;
    #pragma unroll
    for (int m = 16; m; m >>= 1) ss += __shfl_xor_sync(0xffffffffu, ss, m);
    float inv = mult / fmaxf(sqrtf(ss), 1e-12f);
    v.x *= inv * scale[lane * 2];
    v.y *= inv * scale[lane * 2 + 1];
    uint32_t h = pack_bf16(v.x, v.y);
    dh[(size_t)gw * 32 + lane] = h;
    dl[(size_t)gw * 32 + lane] = residual_pack(h, v.x, v.y);
}

// ---------------------------------------------------------------------------
// 4) V prep: transpose [n][d] -> [d][n] per 64-key tile, emit bf16 hi/lo
// ---------------------------------------------------------------------------
__global__ void v_prep_kernel() {
    __shared__ float tile[64][68];
    int bh = blockIdx.y, n0 = blockIdx.x << 6, tid = threadIdx.x;
    const float* V = g_v + ((size_t)bh * SEQ + n0) * DH;
    #pragma unroll
    for (int i = 0; i < 4; i++) {
        int idx = tid + (i << 8);
        int r = idx >> 4, c4 = idx & 15;
        *(float4*)&tile[r][c4 * 4] = ((const float4*)V)[idx];
    }
    __syncthreads();
    #pragma unroll
    for (int i = 0; i < 8; i++) {
        int idx = tid + (i << 8);
        int d = idx >> 5, kp = idx & 31;
        float v0 = tile[2 * kp][d], v1 = tile[2 * kp + 1][d];
        uint32_t h = pack_bf16(v0, v1);
        size_t oi = ((size_t)bh * DH + d) * (SEQ / 2) + (n0 >> 1) + kp;
        g_vth32[oi] = h;
        g_vtl32[oi] = residual_pack(h, v0, v1);
    }
}

// ---------------------------------------------------------------------------
// 5) Flash attention, mma.sync bf16 3-term compensated
//    grid (SEQ/128=16, B*H=64), 256 threads (8 warps x 16 q-rows)
// ---------------------------------------------------------------------------
__global__ void __launch_bounds__(256, 1) attn_mma_kernel() {
    // [64 rows][72 bf16] = 36 uint32 per row (padded for conflict-free ldsm)
    __shared__ uint32_t smKh[64 * 36];
    __shared__ uint32_t smKl[64 * 36];
    __shared__ uint32_t smVh[64 * 36];   // rows = d, cols = key
    __shared__ uint32_t smVl[64 * 36];

    int tid = threadIdx.x, w = tid >> 5, l = tid & 31;
    int g = l >> 2, c = l & 3;
    int bh = blockIdx.y, q0 = blockIdx.x << 7;

    // ---- Q fragments (loop invariant): aq[kstep][4] ----
    uint32_t aqh[4][4], aql[4][4];
    {
        size_t r0 = (size_t)(bh * SEQ + q0 + 16 * w + g) * 32;
        size_t r1 = r0 + 8 * 32;
        #pragma unroll
        for (int kk = 0; kk < 4; kk++) {
            int cu = (kk << 3) + c;
            aqh[kk][0] = g_qh32[r0 + cu];
            aqh[kk][1] = g_qh32[r1 + cu];
            aqh[kk][2] = g_qh32[r0 + cu + 4];
            aqh[kk][3] = g_qh32[r1 + cu + 4];
            aql[kk][0] = g_ql32[r0 + cu];
            aql[kk][1] = g_ql32[r1 + cu];
            aql[kk][2] = g_ql32[r0 + cu + 4];
            aql[kk][3] = g_ql32[r1 + cu + 4];
        }
    }

    float o[8][4];
    #pragma unroll
    for (int t = 0; t < 8; t++)
        #pragma unroll
        for (int i = 0; i < 4; i++) o[t][i] = 0.0f;
    float lsum0 = 0.0f, lsum1 = 0.0f;

    // ldmatrix per-lane base addresses (byte offsets into padded tiles)
    int lrow = (l & 7) + ((l >> 4) & 1) * 8;   // 0..15
    int lcol = ((l >> 3) & 1) * 8;             // bf16 col 0 or 8
    uint32_t off_l = (uint32_t)(lrow * 72 + lcol) * 2;
    uint32_t aKh = smem_u32(smKh) + off_l;
    uint32_t aKl = smem_u32(smKl) + off_l;
    uint32_t aVh = smem_u32(smVh) + off_l;
    uint32_t aVl = smem_u32(smVl) + off_l;

    const uint32_t* Kh = g_kh32 + (size_t)(bh * SEQ) * 32;
    const uint32_t* Kl = g_kl32 + (size_t)(bh * SEQ) * 32;
    const uint32_t* Vh = g_vth32 + (size_t)bh * DH * (SEQ / 2);
    const uint32_t* Vl = g_vtl32 + (size_t)bh * DH * (SEQ / 2);

    for (int j0 = 0; j0 < SEQ; j0 += 64) {
        __syncthreads();
        // stage K/V hi/lo tiles (64 x 64 bf16 each) via uint4 copies
        #pragma unroll
        for (int i = 0; i < 2; i++) {
            int idx = tid + (i << 8);           // 0..511
            int row = idx >> 3, q4 = idx & 7;
            ((uint4*)smKh)[row * 9 + q4] =
                ((const uint4*)(Kh + (size_t)(j0 + row) * 32))[q4];
            ((uint4*)smKl)[row * 9 + q4] =
                ((const uint4*)(Kl + (size_t)(j0 + row) * 32))[q4];
            ((uint4*)smVh)[row * 9 + q4] =
                ((const uint4*)(Vh + (size_t)row * (SEQ / 2) + (j0 >> 1)))[q4];
            ((uint4*)smVl)[row * 9 + q4] =
                ((const uint4*)(Vl + (size_t)row * (SEQ / 2) + (j0 >> 1)))[q4];
        }
        __syncthreads();

        // ---- S = Q K^T ----
        float s[8][4];
        #pragma unroll
        for (int t = 0; t < 8; t++)
            #pragma unroll
            for (int i = 0; i < 4; i++) s[t][i] = 0.0f;

        #pragma unroll
        for (int kk = 0; kk < 4; kk++) {
            #pragma unroll
            for (int tp = 0; tp < 4; tp++) {
                uint32_t bh4[4], bl4[4];
                uint32_t off = (uint32_t)(tp * 16 * 72 + kk * 16) * 2;
                ldsm4(bh4, aKh + off);
                ldsm4(bl4, aKl + off);
                mma16816(s[2*tp],   aqh[kk], bh4[0], bh4[1]);
                mma16816(s[2*tp],   aql[kk], bh4[0], bh4[1]);
                mma16816(s[2*tp],   aqh[kk], bl4[0], bl4[1]);
                mma16816(s[2*tp+1], aqh[kk], bh4[2], bh4[3]);
                mma16816(s[2*tp+1], aql[kk], bh4[2], bh4[3]);
                mma16816(s[2*tp+1], aqh[kk], bl4[2], bl4[3]);
            }
        }

        // ---- softmax, fixed max = 8; pack P hi/lo straight into A fragments ----
        uint32_t ph[4][4], pl[4][4];
        #pragma unroll
        for (int t = 0; t < 8; t++) {
            float e0 = ex2f(fmaf(s[t][0], 1.4426950408889634f, -11.541560327111707f));
            float e1 = ex2f(fmaf(s[t][1], 1.4426950408889634f, -11.541560327111707f));
            float e2 = ex2f(fmaf(s[t][2], 1.4426950408889634f, -11.541560327111707f));
            float e3 = ex2f(fmaf(s[t][3], 1.4426950408889634f, -11.541560327111707f));
            lsum0 += e0 + e1;
            lsum1 += e2 + e3;
            uint32_t h01 = pack_bf16(e0, e1), h23 = pack_bf16(e2, e3);
            uint32_t l01 = residual_pack(h01, e0, e1);
            uint32_t l23 = residual_pack(h23, e2, e3);
            int kk = t >> 1, half = (t & 1) << 1;
            ph[kk][half] = h01; ph[kk][half + 1] = h23;
            pl[kk][half] = l01; pl[kk][half + 1] = l23;
        }

        // ---- O += P V ----
        #pragma unroll
        for (int kk = 0; kk < 4; kk++) {
            #pragma unroll
            for (int tp = 0; tp < 4; tp++) {
                uint32_t vh4[4], vl4[4];
                uint32_t off = (uint32_t)(tp * 16 * 72 + kk * 16) * 2;
                ldsm4(vh4, aVh + off);
                ldsm4(vl4, aVl + off);
                mma16816(o[2*tp],   ph[kk], vh4[0], vh4[1]);
                mma16816(o[2*tp],   pl[kk], vh4[0], vh4[1]);
                mma16816(o[2*tp],   ph[kk], vl4[0], vl4[1]);
                mma16816(o[2*tp+1], ph[kk], vh4[2], vh4[3]);
                mma16816(o[2*tp+1], pl[kk], vh4[2], vh4[3]);
                mma16816(o[2*tp+1], ph[kk], vl4[2], vl4[3]);
            }
        }
    }

    // ---- epilogue ----
    lsum0 += __shfl_xor_sync(0xffffffffu, lsum0, 1);
    lsum0 += __shfl_xor_sync(0xffffffffu, lsum0, 2);
    lsum1 += __shfl_xor_sync(0xffffffffu, lsum1, 1);
    lsum1 += __shfl_xor_sync(0xffffffffu, lsum1, 2);
    float inv0 = 1.0f / lsum0, inv1 = 1.0f / lsum1;

    int b = bh >> 3, h = bh & 7;
    int nr = q0 + 16 * w + g;
    float* base0 = g_o + (size_t)(b * SEQ + nr) * HID + h * DH;
    float* base1 = g_o + (size_t)(b * SEQ + nr + 8) * HID + h * DH;
    #pragma unroll
    for (int t = 0; t < 8; t++) {
        int dcol = 8 * t + 2 * c;
        *(float2*)(base0 + dcol) = make_float2(o[t][0] * inv0, o[t][1] * inv0);
        *(float2*)(base1 + dcol) = make_float2(o[t][2] * inv1, o[t][3] * inv1);
    }
}

// ---------------------------------------------------------------------------
extern "C" void kernel_launch(void* const* d_in, const int* in_sizes, int n_in,
                              void* d_out, int out_size) {
    const float* x       = (const float*)d_in[0];
    const float* g       = (const float*)d_in[1];
    const float* w_qkv   = (const float*)d_in[2];
    const float* q_scale = (const float*)d_in[3];
    const float* k_scale = (const float*)d_in[4];
    const float* w_out   = (const float*)d_in[5];
    float* out = (float*)d_out;
    (void)in_sizes; (void)n_in; (void)out_size;

    rmsnorm_kernel<<<TOK, 128>>>(x, g);
    qkv_gemm_kernel<<<dim3(QKVN / 128, TOK / 128), 256>>>(w_qkv);
    qk_prep_kernel<<<NROWS / 8, 256>>>(q_scale, 8.0f, 0);   // Q, SCALE folded
    qk_prep_kernel<<<NROWS / 8, 256>>>(k_scale, 1.0f, 1);   // K
    v_prep_kernel<<<dim3(SEQ / 64, BATCH * HEADS), 256>>>();
    attn_mma_kernel<<<dim3(SEQ / 128, BATCH * HEADS), 256>>>();
    out_gemm_kernel<<<dim3(DIM / 128, TOK / 128), 256>>>(w_out, out);
}